// round 7
// baseline (speedup 1.0000x reference)
#include <cuda_runtime.h>
#include <cuda_bf16.h>
#include <cuda_fp16.h>

#define N_NODES 100000
#define N_EDGES 1600000
#define DFEAT   128
#define DEG_CAP 64
#define NB_GEMM 782           // ceil(100000/128)
#define NB_FILL 1563          // ceil(1600000/1024)

typedef unsigned long long u64;
typedef unsigned int u32;

// ---------------- scratch (static __device__, no allocs) ----------------
// g_cnt is zero at module load and re-zeroed by the LAST kernel of every call,
// so every invocation (correctness, capture, each replay) sees cnt==0 on entry.
__device__ __align__(16) __half g_hh[N_NODES * DFEAT];   // post-GEMM features (fp16)
__device__ __align__(16) float g_agg[N_NODES * DFEAT];   // layer-1 output (fp32)
__device__ float g_dinv[N_NODES];
__device__ int   g_cnt[N_NODES];
__device__ int   g_col2[N_NODES * DEG_CAP];              // fixed-capacity CSR

// ---------------- f32x2 helpers (Blackwell packed fp32) ----------------
__device__ __forceinline__ u64 pack2dup(float a) {
    u64 r;
    asm("mov.b64 %0, {%1, %1};" : "=l"(r) : "f"(a));
    return r;
}
__device__ __forceinline__ void fma2(u64 &c, u64 a, u64 b) {
    asm("fma.rn.f32x2 %0, %1, %2, %0;" : "+l"(c) : "l"(a), "l"(b));
}
__device__ __forceinline__ float2 unpack2(u64 v) {
    float2 f;
    asm("mov.b64 {%0, %1}, %2;" : "=f"(f.x), "=f"(f.y) : "l"(v));
    return f;
}

// ---------------- GEMM tile body: g_hh[i][j] = (opt dinv[i] *) sum_k A[i][k]*W[j][k] ----------------
// 128x128 block tile, BK=16, 256 threads, 8x8 per thread, packed f32x2 FMAs.
template <int SCALE>
__device__ __forceinline__ void gemm_tile(const float* __restrict__ A,
                                          const float* __restrict__ W,
                                          int blk) {
    __shared__ __align__(16) float As[16][128];
    __shared__ __align__(16) float Bs[16][128];

    const int tid = threadIdx.x;
    const int tx = tid & 15;   // 16 col groups
    const int ty = tid >> 4;   // 16 row groups
    const int rowBase = blk * 128;

    u64 c[8][4];
    #pragma unroll
    for (int i = 0; i < 8; ++i)
        #pragma unroll
        for (int j = 0; j < 4; ++j) c[i][j] = 0ull;

    for (int t = 0; t < 8; ++t) {
        const int kk = t * 16;
        __syncthreads();
        #pragma unroll
        for (int it = 0; it < 2; ++it) {
            int f = tid + it * 256;           // 0..511 float4 slots
            int r = f >> 2;
            int kc = (f & 3) * 4;
            int row = rowBase + r;
            float4 v = make_float4(0.f, 0.f, 0.f, 0.f);
            if (row < N_NODES)
                v = *reinterpret_cast<const float4*>(&A[row * 128 + kk + kc]);
            As[kc + 0][r] = v.x; As[kc + 1][r] = v.y;
            As[kc + 2][r] = v.z; As[kc + 3][r] = v.w;
            float4 w = *reinterpret_cast<const float4*>(&W[r * 128 + kk + kc]);
            Bs[kc + 0][r] = w.x; Bs[kc + 1][r] = w.y;
            Bs[kc + 2][r] = w.z; Bs[kc + 3][r] = w.w;
        }
        __syncthreads();

        #pragma unroll
        for (int k = 0; k < 16; ++k) {
            const float4 a0 = *reinterpret_cast<const float4*>(&As[k][ty * 8]);
            const float4 a1 = *reinterpret_cast<const float4*>(&As[k][ty * 8 + 4]);
            const u64* bp0 = reinterpret_cast<const u64*>(&Bs[k][tx * 4]);
            const u64* bp1 = reinterpret_cast<const u64*>(&Bs[k][64 + tx * 4]);
            u64 b0 = bp0[0], b1 = bp0[1], b2 = bp1[0], b3 = bp1[1];
            float av[8] = {a0.x, a0.y, a0.z, a0.w, a1.x, a1.y, a1.z, a1.w};
            #pragma unroll
            for (int i = 0; i < 8; ++i) {
                u64 aa = pack2dup(av[i]);
                fma2(c[i][0], aa, b0);
                fma2(c[i][1], aa, b1);
                fma2(c[i][2], aa, b2);
                fma2(c[i][3], aa, b3);
            }
        }
    }

    // epilogue: optional dinv scale, pack to fp16, 8B stores
    #pragma unroll
    for (int i = 0; i < 8; ++i) {
        int row = rowBase + ty * 8 + i;
        if (row < N_NODES) {
            const float sc = SCALE ? g_dinv[row] : 1.0f;
            float2 p0 = unpack2(c[i][0]), p1 = unpack2(c[i][1]);
            __half2 h0 = __floats2half2_rn(p0.x * sc, p0.y * sc);
            __half2 h1 = __floats2half2_rn(p1.x * sc, p1.y * sc);
            uint2 o0;
            o0.x = *reinterpret_cast<u32*>(&h0);
            o0.y = *reinterpret_cast<u32*>(&h1);
            *reinterpret_cast<uint2*>(&g_hh[row * 128 + tx * 4]) = o0;
            float2 p2 = unpack2(c[i][2]), p3 = unpack2(c[i][3]);
            __half2 h2 = __floats2half2_rn(p2.x * sc, p2.y * sc);
            __half2 h3 = __floats2half2_rn(p3.x * sc, p3.y * sc);
            uint2 o1;
            o1.x = *reinterpret_cast<u32*>(&h2);
            o1.y = *reinterpret_cast<u32*>(&h3);
            *reinterpret_cast<uint2*>(&g_hh[row * 128 + 64 + tx * 4]) = o1;
        }
    }
}

// ---------------- K1: heterogeneous {GEMM1 (unscaled) || edge fill} ----------------
__global__ __launch_bounds__(256, 2)
void k_mega(const float* __restrict__ x, const float* __restrict__ W1,
            const int* __restrict__ src, const int* __restrict__ dst) {
    if (blockIdx.x < NB_GEMM) {
        gemm_tile<0>(x, W1, blockIdx.x);
    } else {
        int e = (blockIdx.x - NB_GEMM) * 1024 + threadIdx.x;
        #pragma unroll
        for (int it = 0; it < 4; ++it, e += 256) {
            if (e < N_EDGES) {
                int s = src[e];
                int d = dst[e];
                int slot = atomicAdd(&g_cnt[d], 1);
                if (slot < DEG_CAP) g_col2[(d << 6) + slot] = s;
            }
        }
    }
}

// ---------------- K2: dinv ----------------
__global__ void k_dinv() {
    int i = blockIdx.x * 256 + threadIdx.x;
    if (i < N_NODES) g_dinv[i] = rsqrtf((float)(g_cnt[i] + 1));  // +1 self loop
}

// ---------------- K4: GEMM2 (dinv-scaled epilogue) ----------------
__global__ __launch_bounds__(256, 2)
void k_gemm2(const float* __restrict__ W2) {
    gemm_tile<1>(g_agg, W2, blockIdx.x);
}

// ---------------- Aggregate ----------------
// WEIGHTED=1 (layer1): h unscaled -> acc = h[d]*dd + sum h[s]*dinv[s]; out = acc*dd + b + p
// WEIGHTED=0 (layer2): h pre-scaled -> acc = hs[d] + sum hs[s];        out = acc*dd + b + p
//                      also zeroes g_cnt for the next invocation.
template <int WEIGHTED, int ZERO_CNT>
__global__ __launch_bounds__(256)
void k_agg(const float* __restrict__ bias, const float* __restrict__ perturb,
           float* __restrict__ outp) {
    int gw = (blockIdx.x * 256 + threadIdx.x) >> 5;
    if (gw >= N_NODES) return;
    const int lane = threadIdx.x & 31;
    const uint2* __restrict__ hv = reinterpret_cast<const uint2*>(g_hh);

    const int d = gw;
    const float dd = g_dinv[d];
    int cnt = g_cnt[d];
    if (ZERO_CNT) {
        if (lane == 0) g_cnt[d] = 0;
    }
    if (cnt > DEG_CAP) cnt = DEG_CAP;

    uint2 u = hv[d * 32 + lane];              // self loop
    float2 f0 = __half22float2(*reinterpret_cast<__half2*>(&u.x));
    float2 f1 = __half22float2(*reinterpret_cast<__half2*>(&u.y));
    float selfw = WEIGHTED ? dd : 1.0f;
    float ax = f0.x * selfw, ay = f0.y * selfw, az = f1.x * selfw, aw = f1.y * selfw;

    const int* __restrict__ cols = &g_col2[d << 6];
    int j = 0;
    for (; j + 4 <= cnt; j += 4) {
        int s0 = cols[j + 0], s1 = cols[j + 1], s2 = cols[j + 2], s3 = cols[j + 3];
        uint2 u0 = hv[s0 * 32 + lane];
        uint2 u1 = hv[s1 * 32 + lane];
        uint2 u2 = hv[s2 * 32 + lane];
        uint2 u3 = hv[s3 * 32 + lane];
        float w0 = 1.f, w1 = 1.f, w2 = 1.f, w3 = 1.f;
        if (WEIGHTED) { w0 = g_dinv[s0]; w1 = g_dinv[s1]; w2 = g_dinv[s2]; w3 = g_dinv[s3]; }
        float2 a0 = __half22float2(*reinterpret_cast<__half2*>(&u0.x));
        float2 b0 = __half22float2(*reinterpret_cast<__half2*>(&u0.y));
        float2 a1 = __half22float2(*reinterpret_cast<__half2*>(&u1.x));
        float2 b1 = __half22float2(*reinterpret_cast<__half2*>(&u1.y));
        float2 a2 = __half22float2(*reinterpret_cast<__half2*>(&u2.x));
        float2 b2 = __half22float2(*reinterpret_cast<__half2*>(&u2.y));
        float2 a3 = __half22float2(*reinterpret_cast<__half2*>(&u3.x));
        float2 b3 = __half22float2(*reinterpret_cast<__half2*>(&u3.y));
        if (WEIGHTED) {
            ax += a0.x * w0 + a1.x * w1 + a2.x * w2 + a3.x * w3;
            ay += a0.y * w0 + a1.y * w1 + a2.y * w2 + a3.y * w3;
            az += b0.x * w0 + b1.x * w1 + b2.x * w2 + b3.x * w3;
            aw += b0.y * w0 + b1.y * w1 + b2.y * w2 + b3.y * w3;
        } else {
            ax += a0.x + a1.x + a2.x + a3.x;
            ay += a0.y + a1.y + a2.y + a3.y;
            az += b0.x + b1.x + b2.x + b3.x;
            aw += b0.y + b1.y + b2.y + b3.y;
        }
    }
    for (; j < cnt; ++j) {
        int s = cols[j];
        uint2 uu = hv[s * 32 + lane];
        float w = WEIGHTED ? g_dinv[s] : 1.0f;
        float2 aa = __half22float2(*reinterpret_cast<__half2*>(&uu.x));
        float2 bb = __half22float2(*reinterpret_cast<__half2*>(&uu.y));
        ax += aa.x * w; ay += aa.y * w; az += bb.x * w; aw += bb.y * w;
    }

    float4 b = reinterpret_cast<const float4*>(bias)[lane];
    float4 p = reinterpret_cast<const float4*>(perturb)[d * 32 + lane];
    float4 o;
    o.x = ax * dd + b.x + p.x;
    o.y = ay * dd + b.y + p.y;
    o.z = az * dd + b.z + p.z;
    o.w = aw * dd + b.w + p.w;
    reinterpret_cast<float4*>(outp)[d * 32 + lane] = o;
}

// ---------------- launch ----------------
extern "C" void kernel_launch(void* const* d_in, const int* in_sizes, int n_in,
                              void* d_out, int out_size) {
    const float* x  = (const float*)d_in[0];
    const int*   ei = (const int*)d_in[1];
    const float* pf = (const float*)d_in[2];
    const float* pl = (const float*)d_in[3];
    const float* W1 = (const float*)d_in[4];
    const float* b1 = (const float*)d_in[5];
    const float* W2 = (const float*)d_in[6];
    const float* b2 = (const float*)d_in[7];
    float* out = (float*)d_out;
    const int* src = ei;
    const int* dst = ei + N_EDGES;

    const int nb_nodes = (N_NODES + 255) / 256;       // 391
    const int nb_agg   = (N_NODES + 7) / 8;           // 12500

    float* aggp;
    cudaGetSymbolAddress((void**)&aggp, g_agg);       // host-side query, capture-safe

    // K1: GEMM1 (unscaled, independent of graph) overlapped with edge-bucket fill
    k_mega<<<NB_GEMM + NB_FILL, 256>>>(x, W1, src, dst);
    // K2: dinv from final counts
    k_dinv<<<nb_nodes, 256>>>();
    // K3: layer-1 aggregate (per-edge dinv weights)
    k_agg<1, 0><<<nb_agg, 256>>>(b1, pf, aggp);
    // K4: GEMM2 (dinv-scaled epilogue)
    k_gemm2<<<NB_GEMM, 256>>>(W2);
    // K5: layer-2 aggregate (unweighted gathers) + re-zero cnt for next invocation
    k_agg<0, 1><<<nb_agg, 256>>>(b2, pl, out);
}

// round 8
// speedup vs baseline: 1.3358x; 1.3358x over previous
#include <cuda_runtime.h>
#include <cuda_bf16.h>
#include <cuda_fp16.h>

#define N_NODES 100000
#define N_EDGES 1600000
#define DFEAT   128
#define NSCAN_BLOCKS 98   // ceil(100000 / 1024)

typedef unsigned long long u64;
typedef unsigned int u32;

// ---------------- scratch (static __device__, no allocs) ----------------
__device__ __align__(16) __half g_hh[N_NODES * DFEAT];   // post-GEMM features, fp16, pre-scaled by dinv
__device__ __align__(16) float g_agg[N_NODES * DFEAT];   // post-aggregate (layer1 out, fp32)
__device__ float g_dinv[N_NODES];
__device__ int   g_cnt[N_NODES];
__device__ int   g_fill[N_NODES];
__device__ int   g_rowptr[N_NODES + 1];
__device__ int   g_blocksums[256];
__device__ int   g_col[N_EDGES];

// ---------------- f32x2 helpers (Blackwell packed fp32) ----------------
__device__ __forceinline__ u64 pack2dup(float a) {
    u64 r;
    asm("mov.b64 %0, {%1, %1};" : "=l"(r) : "f"(a));
    return r;
}
__device__ __forceinline__ void fma2(u64 &c, u64 a, u64 b) {
    asm("fma.rn.f32x2 %0, %1, %2, %0;" : "+l"(c) : "l"(a), "l"(b));
}
__device__ __forceinline__ float2 unpack2(u64 v) {
    float2 f;
    asm("mov.b64 {%0, %1}, %2;" : "=f"(f.x), "=f"(f.y) : "l"(v));
    return f;
}

// ---------------- CSR build kernels ----------------
__global__ void k_zero() {
    int i = blockIdx.x * 256 + threadIdx.x;
    if (i < N_NODES) g_cnt[i] = 0;
}

__global__ void k_hist(const int* __restrict__ dst) {
    int e = blockIdx.x * 256 + threadIdx.x;
    if (e < N_EDGES) atomicAdd(&g_cnt[dst[e]], 1);
}

__global__ void k_dinv() {
    int i = blockIdx.x * 256 + threadIdx.x;
    if (i < N_NODES) g_dinv[i] = rsqrtf((float)(g_cnt[i] + 1));  // +1 self loop
}

__global__ void k_scan1() {
    __shared__ int sd[256];
    int tid = threadIdx.x;
    int base = blockIdx.x * 1024 + tid * 4;
    int s = 0;
    #pragma unroll
    for (int c = 0; c < 4; ++c)
        if (base + c < N_NODES) s += g_cnt[base + c];
    sd[tid] = s;
    __syncthreads();
    #pragma unroll
    for (int off = 128; off > 0; off >>= 1) {
        if (tid < off) sd[tid] += sd[tid + off];
        __syncthreads();
    }
    if (tid == 0) g_blocksums[blockIdx.x] = sd[0];
}

__global__ void k_scan2() {
    __shared__ int sh[128];
    int tid = threadIdx.x;
    sh[tid] = (tid < NSCAN_BLOCKS) ? g_blocksums[tid] : 0;
    __syncthreads();
    #pragma unroll
    for (int off = 1; off < 128; off <<= 1) {
        int t = (tid >= off) ? sh[tid - off] : 0;
        __syncthreads();
        sh[tid] += t;
        __syncthreads();
    }
    int excl = (tid == 0) ? 0 : sh[tid - 1];
    if (tid < NSCAN_BLOCKS) g_blocksums[tid] = excl;
    if (tid == 0) g_rowptr[N_NODES] = N_EDGES;
}

__global__ void k_scan3() {
    __shared__ int sh[256];
    int tid = threadIdx.x;
    int base = blockIdx.x * 1024 + tid * 4;
    int c0 = 0, c1 = 0, c2 = 0, c3 = 0;
    if (base + 0 < N_NODES) c0 = g_cnt[base + 0];
    if (base + 1 < N_NODES) c1 = g_cnt[base + 1];
    if (base + 2 < N_NODES) c2 = g_cnt[base + 2];
    if (base + 3 < N_NODES) c3 = g_cnt[base + 3];
    sh[tid] = c0 + c1 + c2 + c3;
    __syncthreads();
    #pragma unroll
    for (int off = 1; off < 256; off <<= 1) {
        int t = (tid >= off) ? sh[tid - off] : 0;
        __syncthreads();
        sh[tid] += t;
        __syncthreads();
    }
    int excl = (tid == 0) ? 0 : sh[tid - 1];
    int e = g_blocksums[blockIdx.x] + excl;
    if (base + 0 < N_NODES) { g_rowptr[base + 0] = e;               g_fill[base + 0] = e; }
    if (base + 1 < N_NODES) { g_rowptr[base + 1] = e + c0;           g_fill[base + 1] = e + c0; }
    if (base + 2 < N_NODES) { g_rowptr[base + 2] = e + c0 + c1;      g_fill[base + 2] = e + c0 + c1; }
    if (base + 3 < N_NODES) { g_rowptr[base + 3] = e + c0 + c1 + c2; g_fill[base + 3] = e + c0 + c1 + c2; }
}

__global__ void k_fill(const int* __restrict__ src, const int* __restrict__ dst) {
    int e = blockIdx.x * 256 + threadIdx.x;
    if (e < N_EDGES) {
        int p = atomicAdd(&g_fill[dst[e]], 1);
        g_col[p] = src[e];
    }
}

// ---------------- GEMM: g_hh[i][j] = (half) dinv[i] * sum_k A[i][k] * W[j][k] ----------------
// 128(M) x 64(N) block tile, BK=16, 256 threads, 8x4 per thread -> 16 u64 accum, occ 3.
template <int PHASE>
__global__ __launch_bounds__(256, 3)
void k_gemm(const float* __restrict__ Aext, const float* __restrict__ W) {
    const float* __restrict__ A = (PHASE == 0) ? Aext : g_agg;

    __shared__ __align__(16) float As[16][128];
    __shared__ __align__(16) float Bs[16][64];

    const int tid = threadIdx.x;
    const int tx = tid & 15;   // 16 col groups of 4
    const int ty = tid >> 4;   // 16 row groups of 8
    const int mblk = blockIdx.x >> 1;
    const int noff = (blockIdx.x & 1) * 64;   // which 64-col half of W/output
    const int rowBase = mblk * 128;

    u64 c[8][2];
    #pragma unroll
    for (int i = 0; i < 8; ++i) { c[i][0] = 0ull; c[i][1] = 0ull; }

    for (int t = 0; t < 8; ++t) {
        const int kk = t * 16;
        __syncthreads();
        // A tile: 512 float4 slots over 2 iterations
        #pragma unroll
        for (int it = 0; it < 2; ++it) {
            int f = tid + it * 256;
            int r = f >> 2;
            int kc = (f & 3) * 4;
            int row = rowBase + r;
            float4 v = make_float4(0.f, 0.f, 0.f, 0.f);
            if (row < N_NODES)
                v = *reinterpret_cast<const float4*>(&A[row * 128 + kk + kc]);
            As[kc + 0][r] = v.x; As[kc + 1][r] = v.y;
            As[kc + 2][r] = v.z; As[kc + 3][r] = v.w;
        }
        // B tile: 64 rows x 16 k = 256 float4 slots, 1 iteration
        {
            int r = tid >> 2;              // 0..63 (W row within half)
            int kc = (tid & 3) * 4;
            float4 w = *reinterpret_cast<const float4*>(&W[(noff + r) * 128 + kk + kc]);
            Bs[kc + 0][r] = w.x; Bs[kc + 1][r] = w.y;
            Bs[kc + 2][r] = w.z; Bs[kc + 3][r] = w.w;
        }
        __syncthreads();

        #pragma unroll
        for (int k = 0; k < 16; ++k) {
            const float4 a0 = *reinterpret_cast<const float4*>(&As[k][ty * 8]);
            const float4 a1 = *reinterpret_cast<const float4*>(&As[k][ty * 8 + 4]);
            const u64* bp = reinterpret_cast<const u64*>(&Bs[k][tx * 4]);
            u64 b0 = bp[0], b1 = bp[1];
            float av[8] = {a0.x, a0.y, a0.z, a0.w, a1.x, a1.y, a1.z, a1.w};
            #pragma unroll
            for (int i = 0; i < 8; ++i) {
                u64 aa = pack2dup(av[i]);
                fma2(c[i][0], aa, b0);
                fma2(c[i][1], aa, b1);
            }
        }
    }

    // epilogue: scale by dinv[row], pack to fp16, one 8B store per row
    #pragma unroll
    for (int i = 0; i < 8; ++i) {
        int row = rowBase + ty * 8 + i;
        if (row < N_NODES) {
            const float sc = g_dinv[row];
            float2 p0 = unpack2(c[i][0]), p1 = unpack2(c[i][1]);
            __half2 h0 = __floats2half2_rn(p0.x * sc, p0.y * sc);
            __half2 h1 = __floats2half2_rn(p1.x * sc, p1.y * sc);
            uint2 o0;
            o0.x = *reinterpret_cast<u32*>(&h0);
            o0.y = *reinterpret_cast<u32*>(&h1);
            *reinterpret_cast<uint2*>(&g_hh[row * 128 + noff + tx * 4]) = o0;
        }
    }
}

// ---------------- Aggregate: out[d] = dinv[d]*(sum_{s in N(d)} hs[s] + hs[d]) + b + perturb
// hs = h pre-scaled by dinv, stored fp16. One warp per node, 4 halfs (8B) per lane.
template <int PHASE>
__global__ __launch_bounds__(256)
void k_agg(const float* __restrict__ bias, const float* __restrict__ perturb,
           float* __restrict__ outParam) {
    int gw = (blockIdx.x * 256 + threadIdx.x) >> 5;
    if (gw >= N_NODES) return;
    const int lane = threadIdx.x & 31;
    const uint2* __restrict__ hv = reinterpret_cast<const uint2*>(g_hh);
    float* __restrict__ outp = (PHASE == 0) ? g_agg : outParam;

    const int d = gw;
    const float dd = g_dinv[d];

    uint2 u = hv[d * 32 + lane];              // self loop (already scaled by dinv[d])
    float2 f0 = __half22float2(*reinterpret_cast<__half2*>(&u.x));
    float2 f1 = __half22float2(*reinterpret_cast<__half2*>(&u.y));
    float ax = f0.x, ay = f0.y, az = f1.x, aw = f1.y;

    int j = g_rowptr[d];
    const int end = g_rowptr[d + 1];
    for (; j + 4 <= end; j += 4) {
        int s0 = g_col[j + 0], s1 = g_col[j + 1], s2 = g_col[j + 2], s3 = g_col[j + 3];
        uint2 u0 = hv[s0 * 32 + lane];
        uint2 u1 = hv[s1 * 32 + lane];
        uint2 u2 = hv[s2 * 32 + lane];
        uint2 u3 = hv[s3 * 32 + lane];
        float2 a0 = __half22float2(*reinterpret_cast<__half2*>(&u0.x));
        float2 b0 = __half22float2(*reinterpret_cast<__half2*>(&u0.y));
        float2 a1 = __half22float2(*reinterpret_cast<__half2*>(&u1.x));
        float2 b1 = __half22float2(*reinterpret_cast<__half2*>(&u1.y));
        float2 a2 = __half22float2(*reinterpret_cast<__half2*>(&u2.x));
        float2 b2 = __half22float2(*reinterpret_cast<__half2*>(&u2.y));
        float2 a3 = __half22float2(*reinterpret_cast<__half2*>(&u3.x));
        float2 b3 = __half22float2(*reinterpret_cast<__half2*>(&u3.y));
        ax += a0.x + a1.x + a2.x + a3.x;
        ay += a0.y + a1.y + a2.y + a3.y;
        az += b0.x + b1.x + b2.x + b3.x;
        aw += b0.y + b1.y + b2.y + b3.y;
    }
    for (; j < end; ++j) {
        int s = g_col[j];
        uint2 uu = hv[s * 32 + lane];
        float2 aa = __half22float2(*reinterpret_cast<__half2*>(&uu.x));
        float2 bb = __half22float2(*reinterpret_cast<__half2*>(&uu.y));
        ax += aa.x; ay += aa.y; az += bb.x; aw += bb.y;
    }

    float4 b = reinterpret_cast<const float4*>(bias)[lane];
    float4 p = reinterpret_cast<const float4*>(perturb)[d * 32 + lane];
    float4 o;
    o.x = ax * dd + b.x + p.x;
    o.y = ay * dd + b.y + p.y;
    o.z = az * dd + b.z + p.z;
    o.w = aw * dd + b.w + p.w;
    reinterpret_cast<float4*>(outp)[d * 32 + lane] = o;
}

// ---------------- launch ----------------
extern "C" void kernel_launch(void* const* d_in, const int* in_sizes, int n_in,
                              void* d_out, int out_size) {
    const float* x  = (const float*)d_in[0];
    const int*   ei = (const int*)d_in[1];
    const float* pf = (const float*)d_in[2];
    const float* pl = (const float*)d_in[3];
    const float* W1 = (const float*)d_in[4];
    const float* b1 = (const float*)d_in[5];
    const float* W2 = (const float*)d_in[6];
    const float* b2 = (const float*)d_in[7];
    float* out = (float*)d_out;
    const int* src = ei;
    const int* dst = ei + N_EDGES;

    const int nb_nodes = (N_NODES + 255) / 256;       // 391
    const int nb_edges = (N_EDGES + 255) / 256;       // 6250
    const int nb_gemm  = ((N_NODES + 127) / 128) * 2; // 1564 (128x64 tiles)
    const int nb_agg   = (N_NODES + 7) / 8;           // 12500

    // CSR + norm build (per call; deterministic work)
    k_zero<<<nb_nodes, 256>>>();
    k_hist<<<nb_edges, 256>>>(dst);
    k_dinv<<<nb_nodes, 256>>>();
    k_scan1<<<NSCAN_BLOCKS, 256>>>();
    k_scan2<<<1, 128>>>();
    k_scan3<<<NSCAN_BLOCKS, 256>>>();
    k_fill<<<nb_edges, 256>>>(src, dst);

    // layer 1
    k_gemm<0><<<nb_gemm, 256>>>(x, W1);
    k_agg<0><<<nb_agg, 256>>>(b1, pf, nullptr);
    // layer 2
    k_gemm<1><<<nb_gemm, 256>>>(nullptr, W2);
    k_agg<1><<<nb_agg, 256>>>(b2, pl, out);
}